// round 4
// baseline (speedup 1.0000x reference)
#include <cuda_runtime.h>
#include <math.h>
#include <stdint.h>

// Problem constants
#define S_ 2048
#define H_ 512
#define F_ 2048
#define T_ 32
#define L_ 6
#define START_TAG 30
#define STOP_TAG 31
#define NEG_ (-10000.0f)

typedef unsigned long long u64;

// ---------------------------------------------------------------------------
// Static device scratch (no allocations allowed)
// ---------------------------------------------------------------------------
__device__ float g_x[S_ * H_];        // embeddings (kept for decoder input)
__device__ float g_h[S_ * H_];        // encoder stream
__device__ float g_mem[S_ * H_];      // encoder memory
__device__ float g_y[S_ * H_];        // decoder stream
__device__ float g_qkv[3 * S_ * H_];  // q,k,v packed
__device__ float g_t2[S_ * H_];       // att @ v
__device__ float g_tmp[S_ * H_];      // pre-LN sublayer output
__device__ float g_att[S_ * S_];      // attention scores (16 MB)
__device__ float g_ff[S_ * F_];       // FFN hidden (16 MB)
__device__ float g_feats[S_ * T_];
__device__ int   g_bptr[S_ * T_];

// Packed fp32x2 FMA helpers (Blackwell FFMA2; bit-exact IEEE fp32)
#define FFMA2(acc, ap, bp) \
    asm("fma.rn.f32x2 %0, %1, %2, %0;" : "+l"(acc) : "l"(ap), "l"(bp))
#define PACK2(dst, f) \
    asm("mov.b64 %0, {%1, %1};" : "=l"(dst) : "f"(f))
#define UNPACK2(lo, hi, src) \
    asm("mov.b64 {%0, %1}, %2;" : "=f"(lo), "=f"(hi) : "l"(src))

// ===========================================================================
// Double-buffered SGEMM with packed f32x2 FMAs.
// C[M,N] = alpha * A[M,K] @ B (+ bias), optional ReLU.
// TRANSB=false: B is [K,N]. TRANSB=true: B is [N,K].
// 128x128x16 tile, 256 threads, 8x8 per thread. M%128==0, N%128==0, K%16==0.
// ===========================================================================
template <bool TRANSB, bool RELU>
__device__ __forceinline__ void gemm128db_body(
    const float* __restrict__ A, const float* __restrict__ B,
    const float* __restrict__ bias, float* __restrict__ C,
    int N, int K, float alpha)
{
    __shared__ float As[2][16][132];
    __shared__ float Bs[2][16][132];

    const int tid = threadIdx.x;
    const int m0 = blockIdx.y * 128;
    const int n0 = blockIdx.x * 128;

    const int ar = tid >> 2;           // 0..63
    const int ac = (tid & 3) * 4;      // 0,4,8,12
    const int br = tid >> 4;           // 0..15
    const int bc = (tid & 15) * 8;     // 0..120
    const int ty = (tid >> 4) * 8;
    const int tx = (tid & 15) * 8;

    const float* Arow0 = A + (size_t)(m0 + ar) * K + ac;
    const float* Arow1 = A + (size_t)(m0 + ar + 64) * K + ac;

    float4 ra0, ra1, rb0, rb1;

    // ---- prologue: load tile 0 ----
    ra0 = *(const float4*)(Arow0);
    ra1 = *(const float4*)(Arow1);
    if (!TRANSB) {
        rb0 = *(const float4*)(B + (size_t)br * N + n0 + bc);
        rb1 = *(const float4*)(B + (size_t)br * N + n0 + bc + 4);
    } else {
        rb0 = *(const float4*)(B + (size_t)(n0 + ar) * K + ac);
        rb1 = *(const float4*)(B + (size_t)(n0 + ar + 64) * K + ac);
    }
    As[0][ac + 0][ar] = ra0.x; As[0][ac + 1][ar] = ra0.y;
    As[0][ac + 2][ar] = ra0.z; As[0][ac + 3][ar] = ra0.w;
    As[0][ac + 0][ar + 64] = ra1.x; As[0][ac + 1][ar + 64] = ra1.y;
    As[0][ac + 2][ar + 64] = ra1.z; As[0][ac + 3][ar + 64] = ra1.w;
    if (!TRANSB) {
        *(float4*)&Bs[0][br][bc]     = rb0;
        *(float4*)&Bs[0][br][bc + 4] = rb1;
    } else {
        Bs[0][ac + 0][ar] = rb0.x; Bs[0][ac + 1][ar] = rb0.y;
        Bs[0][ac + 2][ar] = rb0.z; Bs[0][ac + 3][ar] = rb0.w;
        Bs[0][ac + 0][ar + 64] = rb1.x; Bs[0][ac + 1][ar + 64] = rb1.y;
        Bs[0][ac + 2][ar + 64] = rb1.z; Bs[0][ac + 3][ar + 64] = rb1.w;
    }

    u64 acc[8][4];
#pragma unroll
    for (int i = 0; i < 8; i++)
#pragma unroll
        for (int j = 0; j < 4; j++) acc[i][j] = 0ULL;

    const int nt = K >> 4;
    for (int t = 0; t < nt; t++) {
        const int cur = t & 1;
        __syncthreads();

        // issue global loads for next tile (latency hidden behind compute)
        if (t + 1 < nt) {
            const int k0 = (t + 1) << 4;
            ra0 = *(const float4*)(Arow0 + k0);
            ra1 = *(const float4*)(Arow1 + k0);
            if (!TRANSB) {
                rb0 = *(const float4*)(B + (size_t)(k0 + br) * N + n0 + bc);
                rb1 = *(const float4*)(B + (size_t)(k0 + br) * N + n0 + bc + 4);
            } else {
                rb0 = *(const float4*)(B + (size_t)(n0 + ar) * K + k0 + ac);
                rb1 = *(const float4*)(B + (size_t)(n0 + ar + 64) * K + k0 + ac);
            }
        }

        // compute on current buffer (packed f32x2: 32 FFMA2 per kk)
#pragma unroll
        for (int kk = 0; kk < 16; kk++) {
            float a[8];
            *(float4*)&a[0] = *(const float4*)&As[cur][kk][ty];
            *(float4*)&a[4] = *(const float4*)&As[cur][kk][ty + 4];
            const u64* bp = (const u64*)&Bs[cur][kk][tx];
            u64 b0 = bp[0], b1 = bp[1], b2 = bp[2], b3 = bp[3];
#pragma unroll
            for (int i = 0; i < 8; i++) {
                u64 ap;
                PACK2(ap, a[i]);
                FFMA2(acc[i][0], ap, b0);
                FFMA2(acc[i][1], ap, b1);
                FFMA2(acc[i][2], ap, b2);
                FFMA2(acc[i][3], ap, b3);
            }
        }

        // stage next tile into the other buffer
        if (t + 1 < nt) {
            const int nb = cur ^ 1;
            As[nb][ac + 0][ar] = ra0.x; As[nb][ac + 1][ar] = ra0.y;
            As[nb][ac + 2][ar] = ra0.z; As[nb][ac + 3][ar] = ra0.w;
            As[nb][ac + 0][ar + 64] = ra1.x; As[nb][ac + 1][ar + 64] = ra1.y;
            As[nb][ac + 2][ar + 64] = ra1.z; As[nb][ac + 3][ar + 64] = ra1.w;
            if (!TRANSB) {
                *(float4*)&Bs[nb][br][bc]     = rb0;
                *(float4*)&Bs[nb][br][bc + 4] = rb1;
            } else {
                Bs[nb][ac + 0][ar] = rb0.x; Bs[nb][ac + 1][ar] = rb0.y;
                Bs[nb][ac + 2][ar] = rb0.z; Bs[nb][ac + 3][ar] = rb0.w;
                Bs[nb][ac + 0][ar + 64] = rb1.x; Bs[nb][ac + 1][ar + 64] = rb1.y;
                Bs[nb][ac + 2][ar + 64] = rb1.z; Bs[nb][ac + 3][ar + 64] = rb1.w;
            }
        }
    }

    // ---- epilogue ----
#pragma unroll
    for (int i = 0; i < 8; i++) {
        float* crow = C + (size_t)(m0 + ty + i) * N + n0 + tx;
        float c[8];
#pragma unroll
        for (int j = 0; j < 4; j++)
            UNPACK2(c[2 * j], c[2 * j + 1], acc[i][j]);
#pragma unroll
        for (int j = 0; j < 8; j += 4) {
            float4 o;
            o.x = c[j + 0] * alpha;
            o.y = c[j + 1] * alpha;
            o.z = c[j + 2] * alpha;
            o.w = c[j + 3] * alpha;
            if (bias) {
                o.x += bias[n0 + tx + j + 0];
                o.y += bias[n0 + tx + j + 1];
                o.z += bias[n0 + tx + j + 2];
                o.w += bias[n0 + tx + j + 3];
            }
            if (RELU) {
                o.x = fmaxf(o.x, 0.f); o.y = fmaxf(o.y, 0.f);
                o.z = fmaxf(o.z, 0.f); o.w = fmaxf(o.w, 0.f);
            }
            *(float4*)(crow + j) = o;
        }
    }
}

template <bool TRANSB, bool RELU>
__global__ __launch_bounds__(256) void gemm128_kernel(
    const float* __restrict__ A, const float* __restrict__ B,
    const float* __restrict__ bias, float* __restrict__ C,
    int N, int K, float alpha)
{
    gemm128db_body<TRANSB, RELU>(A, B, bias, C, N, K, alpha);
}

// Batched QKV projection: blockIdx.z selects q (from qin) / k / v (from kvin).
__global__ __launch_bounds__(256) void gemm_qkv_kernel(
    const float* __restrict__ qin, const float* __restrict__ kvin,
    const float* __restrict__ W, const float* __restrict__ Bv,
    float* __restrict__ qkv)
{
    const int z = blockIdx.z;
    const float* A = (z == 0) ? qin : kvin;
    gemm128db_body<false, false>(A, W + (size_t)z * H_ * H_, Bv + (size_t)z * H_,
                                 qkv + (size_t)z * S_ * H_, H_, H_, 1.f);
}

// ---- 128x64x16 double-buffered, 256 threads, 8x4 per thread. B is [K,N].
template <bool RELU>
__global__ __launch_bounds__(256) void gemm12864_kernel(
    const float* __restrict__ A, const float* __restrict__ B,
    const float* __restrict__ bias, float* __restrict__ C,
    int N, int K, float alpha)
{
    __shared__ float As[2][16][132];
    __shared__ float Bs[2][16][68];

    const int tid = threadIdx.x;
    const int m0 = blockIdx.y * 128;
    const int n0 = blockIdx.x * 64;

    const int ar = tid >> 2;           // 0..63
    const int ac = (tid & 3) * 4;      // 0,4,8,12
    const int br = tid >> 4;           // 0..15
    const int bc = (tid & 15) * 4;     // 0..60
    const int ty = (tid >> 4) * 8;
    const int tx = (tid & 15) * 4;

    const float* Arow0 = A + (size_t)(m0 + ar) * K + ac;
    const float* Arow1 = A + (size_t)(m0 + ar + 64) * K + ac;

    float4 ra0, ra1, rb0;

    ra0 = *(const float4*)(Arow0);
    ra1 = *(const float4*)(Arow1);
    rb0 = *(const float4*)(B + (size_t)br * N + n0 + bc);

    As[0][ac + 0][ar] = ra0.x; As[0][ac + 1][ar] = ra0.y;
    As[0][ac + 2][ar] = ra0.z; As[0][ac + 3][ar] = ra0.w;
    As[0][ac + 0][ar + 64] = ra1.x; As[0][ac + 1][ar + 64] = ra1.y;
    As[0][ac + 2][ar + 64] = ra1.z; As[0][ac + 3][ar + 64] = ra1.w;
    *(float4*)&Bs[0][br][bc] = rb0;

    u64 acc[8][2];
#pragma unroll
    for (int i = 0; i < 8; i++) {
        acc[i][0] = 0ULL;
        acc[i][1] = 0ULL;
    }

    const int nt = K >> 4;
    for (int t = 0; t < nt; t++) {
        const int cur = t & 1;
        __syncthreads();

        if (t + 1 < nt) {
            const int k0 = (t + 1) << 4;
            ra0 = *(const float4*)(Arow0 + k0);
            ra1 = *(const float4*)(Arow1 + k0);
            rb0 = *(const float4*)(B + (size_t)(k0 + br) * N + n0 + bc);
        }

#pragma unroll
        for (int kk = 0; kk < 16; kk++) {
            float a[8];
            *(float4*)&a[0] = *(const float4*)&As[cur][kk][ty];
            *(float4*)&a[4] = *(const float4*)&As[cur][kk][ty + 4];
            const u64* bp = (const u64*)&Bs[cur][kk][tx];
            u64 b0 = bp[0], b1 = bp[1];
#pragma unroll
            for (int i = 0; i < 8; i++) {
                u64 ap;
                PACK2(ap, a[i]);
                FFMA2(acc[i][0], ap, b0);
                FFMA2(acc[i][1], ap, b1);
            }
        }

        if (t + 1 < nt) {
            const int nb = cur ^ 1;
            As[nb][ac + 0][ar] = ra0.x; As[nb][ac + 1][ar] = ra0.y;
            As[nb][ac + 2][ar] = ra0.z; As[nb][ac + 3][ar] = ra0.w;
            As[nb][ac + 0][ar + 64] = ra1.x; As[nb][ac + 1][ar + 64] = ra1.y;
            As[nb][ac + 2][ar + 64] = ra1.z; As[nb][ac + 3][ar + 64] = ra1.w;
            *(float4*)&Bs[nb][br][bc] = rb0;
        }
    }

#pragma unroll
    for (int i = 0; i < 8; i++) {
        float c[4];
        UNPACK2(c[0], c[1], acc[i][0]);
        UNPACK2(c[2], c[3], acc[i][1]);
        float4 o;
        o.x = c[0] * alpha;
        o.y = c[1] * alpha;
        o.z = c[2] * alpha;
        o.w = c[3] * alpha;
        if (bias) {
            o.x += bias[n0 + tx + 0];
            o.y += bias[n0 + tx + 1];
            o.z += bias[n0 + tx + 2];
            o.w += bias[n0 + tx + 3];
        }
        if (RELU) {
            o.x = fmaxf(o.x, 0.f); o.y = fmaxf(o.y, 0.f);
            o.z = fmaxf(o.z, 0.f); o.w = fmaxf(o.w, 0.f);
        }
        *(float4*)(C + (size_t)(m0 + ty + i) * N + n0 + tx) = o;
    }
}

// ---- 64x64x16 bounds-checked fallback (used for h2t, N=32) ----
#define BM 64
#define BN 64
#define BK 16

template <bool TRANSB, bool RELU>
__global__ __launch_bounds__(256) void gemm64_kernel(
    const float* __restrict__ A, const float* __restrict__ B,
    const float* __restrict__ bias, float* __restrict__ C,
    int M, int N, int K, float alpha)
{
    __shared__ float As[BK][BM];
    __shared__ float Bs[BK][BN + 4];

    const int tid = threadIdx.x;
    const int m0 = blockIdx.y * BM;
    const int n0 = blockIdx.x * BN;
    const int tx = tid & 15;
    const int ty = tid >> 4;

    float acc[4][4];
#pragma unroll
    for (int i = 0; i < 4; i++)
#pragma unroll
        for (int j = 0; j < 4; j++) acc[i][j] = 0.f;

    for (int k0 = 0; k0 < K; k0 += BK) {
        {
            const int row = tid >> 2;
            const int col = (tid & 3) * 4;
            float4 av = make_float4(0.f, 0.f, 0.f, 0.f);
            if (m0 + row < M)
                av = *(const float4*)(A + (size_t)(m0 + row) * K + k0 + col);
            As[col + 0][row] = av.x;
            As[col + 1][row] = av.y;
            As[col + 2][row] = av.z;
            As[col + 3][row] = av.w;
        }
        if (!TRANSB) {
            const int row = tid >> 4;
            const int col = (tid & 15) * 4;
            float4 bv;
            if (n0 + col + 3 < N) {
                bv = *(const float4*)(B + (size_t)(k0 + row) * N + n0 + col);
            } else {
                float t0 = (n0 + col + 0 < N) ? B[(size_t)(k0 + row) * N + n0 + col + 0] : 0.f;
                float t1 = (n0 + col + 1 < N) ? B[(size_t)(k0 + row) * N + n0 + col + 1] : 0.f;
                float t2 = (n0 + col + 2 < N) ? B[(size_t)(k0 + row) * N + n0 + col + 2] : 0.f;
                float t3 = (n0 + col + 3 < N) ? B[(size_t)(k0 + row) * N + n0 + col + 3] : 0.f;
                bv = make_float4(t0, t1, t2, t3);
            }
            *(float4*)&Bs[row][col] = bv;
        } else {
            const int row = tid >> 2;
            const int col = (tid & 3) * 4;
            float4 bv = make_float4(0.f, 0.f, 0.f, 0.f);
            if (n0 + row < N)
                bv = *(const float4*)(B + (size_t)(n0 + row) * K + k0 + col);
            Bs[col + 0][row] = bv.x;
            Bs[col + 1][row] = bv.y;
            Bs[col + 2][row] = bv.z;
            Bs[col + 3][row] = bv.w;
        }
        __syncthreads();

#pragma unroll
        for (int kk = 0; kk < BK; kk++) {
            float4 a0 = *(const float4*)&As[kk][ty * 4];
            float4 b0 = *(const float4*)&Bs[kk][tx * 4];
            acc[0][0] += a0.x * b0.x; acc[0][1] += a0.x * b0.y; acc[0][2] += a0.x * b0.z; acc[0][3] += a0.x * b0.w;
            acc[1][0] += a0.y * b0.x; acc[1][1] += a0.y * b0.y; acc[1][2] += a0.y * b0.z; acc[1][3] += a0.y * b0.w;
            acc[2][0] += a0.z * b0.x; acc[2][1] += a0.z * b0.y; acc[2][2] += a0.z * b0.z; acc[2][3] += a0.z * b0.w;
            acc[3][0] += a0.w * b0.x; acc[3][1] += a0.w * b0.y; acc[3][2] += a0.w * b0.z; acc[3][3] += a0.w * b0.w;
        }
        __syncthreads();
    }

#pragma unroll
    for (int i = 0; i < 4; i++) {
        const int row = m0 + ty * 4 + i;
        if (row >= M) continue;
        const int col = n0 + tx * 4;
#pragma unroll
        for (int j = 0; j < 4; j++) {
            if (col + j < N) {
                float o = acc[i][j] * alpha;
                if (bias) o += bias[col + j];
                if (RELU) o = fmaxf(o, 0.f);
                C[(size_t)row * N + col + j] = o;
            }
        }
    }
}

// ---------------------------------------------------------------------------
// Row softmax over N = S_ columns. One block (256 thr) per row, in place.
// ---------------------------------------------------------------------------
__global__ __launch_bounds__(256) void softmax_kernel(float* __restrict__ x)
{
    const int N = S_;
    float* p = x + (size_t)blockIdx.x * N;
    const int tid = threadIdx.x;
    __shared__ float r1[8];
    __shared__ float r2[8];

    float mx = -3.4e38f;
    for (int c = tid; c < N; c += 256) mx = fmaxf(mx, p[c]);
#pragma unroll
    for (int o = 16; o; o >>= 1) mx = fmaxf(mx, __shfl_xor_sync(0xffffffffu, mx, o));
    if ((tid & 31) == 0) r1[tid >> 5] = mx;
    __syncthreads();
    mx = r1[0];
#pragma unroll
    for (int i = 1; i < 8; i++) mx = fmaxf(mx, r1[i]);

    float sum = 0.f;
    for (int c = tid; c < N; c += 256) {
        float e = expf(p[c] - mx);
        p[c] = e;
        sum += e;
    }
#pragma unroll
    for (int o = 16; o; o >>= 1) sum += __shfl_xor_sync(0xffffffffu, sum, o);
    if ((tid & 31) == 0) r2[tid >> 5] = sum;
    __syncthreads();
    sum = 0.f;
#pragma unroll
    for (int i = 0; i < 8; i++) sum += r2[i];
    const float inv = 1.f / sum;
    for (int c = tid; c < N; c += 256) p[c] *= inv;
}

// ---------------------------------------------------------------------------
// LayerNorm over H_=512: out = LN(a (+ res)) * w + b. One warp per row.
// ---------------------------------------------------------------------------
__global__ __launch_bounds__(256) void ln_kernel(
    float* __restrict__ out, const float* __restrict__ a,
    const float* __restrict__ res,
    const float* __restrict__ w, const float* __restrict__ b)
{
    const int gw = (blockIdx.x * blockDim.x + threadIdx.x) >> 5;
    const int lane = threadIdx.x & 31;
    if (gw >= S_) return;

    const float4* ap = (const float4*)(a + (size_t)gw * H_);
    const float4* rp = res ? (const float4*)(res + (size_t)gw * H_) : nullptr;

    float4 xv[4];
    float sum = 0.f;
#pragma unroll
    for (int i = 0; i < 4; i++) {
        float4 vv = ap[i * 32 + lane];
        if (rp) {
            float4 r = rp[i * 32 + lane];
            vv.x += r.x; vv.y += r.y; vv.z += r.z; vv.w += r.w;
        }
        xv[i] = vv;
        sum += vv.x + vv.y + vv.z + vv.w;
    }
#pragma unroll
    for (int o = 16; o; o >>= 1) sum += __shfl_xor_sync(0xffffffffu, sum, o);
    const float mean = sum * (1.f / H_);

    float var = 0.f;
#pragma unroll
    for (int i = 0; i < 4; i++) {
        float dx = xv[i].x - mean; var += dx * dx;
        dx = xv[i].y - mean; var += dx * dx;
        dx = xv[i].z - mean; var += dx * dx;
        dx = xv[i].w - mean; var += dx * dx;
    }
#pragma unroll
    for (int o = 16; o; o >>= 1) var += __shfl_xor_sync(0xffffffffu, var, o);
    const float rs = rsqrtf(var * (1.f / H_) + 1e-5f);

    float4* op = (float4*)(out + (size_t)gw * H_);
    const float4* wp = (const float4*)w;
    const float4* bp = (const float4*)b;
#pragma unroll
    for (int i = 0; i < 4; i++) {
        const int idx = i * 32 + lane;
        float4 wv = wp[idx];
        float4 bv = bp[idx];
        float4 o;
        o.x = (xv[i].x - mean) * rs * wv.x + bv.x;
        o.y = (xv[i].y - mean) * rs * wv.y + bv.y;
        o.z = (xv[i].z - mean) * rs * wv.z + bv.z;
        o.w = (xv[i].w - mean) * rs * wv.w + bv.w;
        op[idx] = o;
    }
}

// ---------------------------------------------------------------------------
// Embedding gather
// ---------------------------------------------------------------------------
__global__ __launch_bounds__(128) void embed_kernel(
    float* __restrict__ x, const int* __restrict__ sent,
    const float* __restrict__ embed)
{
    const int s = blockIdx.x;
    const int t = threadIdx.x;
    const float4* src = (const float4*)(embed + (size_t)sent[s] * H_);
    ((float4*)(x + (size_t)s * H_))[t] = src[t];
}

// ---------------------------------------------------------------------------
// Viterbi: single warp. Matches jnp.argmax first-max semantics via strict >.
// ---------------------------------------------------------------------------
__global__ void viterbi_kernel(const float* __restrict__ feats,
                               const float* __restrict__ trans,
                               int* __restrict__ bptr,
                               float* __restrict__ out, int out_size)
{
    const int j = threadIdx.x;
    __shared__ float fv[T_];
    __shared__ float terms[T_];

    float tr[T_];
#pragma unroll
    for (int i = 0; i < T_; i++) tr[i] = trans[j * T_ + i];

    fv[j] = (j == START_TAG) ? 0.f : NEG_;
    __syncwarp();

    for (int t = 0; t < S_; t++) {
        float best = -3.4e38f;
        int bi = 0;
#pragma unroll
        for (int i = 0; i < T_; i++) {
            float sc = fv[i] + tr[i];
            if (sc > best) { best = sc; bi = i; }
        }
        float nf = best + feats[t * T_ + j];
        bptr[t * T_ + j] = bi;
        __syncwarp();
        fv[j] = nf;
        __syncwarp();
    }

    terms[j] = fv[j] + trans[STOP_TAG * T_ + j];
    __syncwarp();

    if (j == 0) {
        float best = terms[0];
        int bi = 0;
#pragma unroll
        for (int i = 1; i < T_; i++)
            if (terms[i] > best) { best = terms[i]; bi = i; }

        int tag = bi;
        if (out_size >= S_ + 1) {
            out[0] = best;
            for (int t = S_ - 1; t >= 0; t--) {
                out[1 + t] = (float)tag;
                tag = bptr[t * T_ + tag];
            }
        } else if (out_size == S_) {
            for (int t = S_ - 1; t >= 0; t--) {
                out[t] = (float)tag;
                tag = bptr[t * T_ + tag];
            }
        } else {
            out[0] = best;
        }
    }
}

// ---------------------------------------------------------------------------
// Host orchestration
// ---------------------------------------------------------------------------
extern "C" void kernel_launch(void* const* d_in, const int* in_sizes, int n_in,
                              void* d_out, int out_size)
{
    const int*   sentence   = (const int*)  d_in[0];
    const float* embed      = (const float*)d_in[1];
    const float* enc_attn_w = (const float*)d_in[2];
    const float* enc_attn_b = (const float*)d_in[3];
    const float* enc_w1     = (const float*)d_in[4];
    const float* enc_b1     = (const float*)d_in[5];
    const float* enc_w2     = (const float*)d_in[6];
    const float* enc_b2     = (const float*)d_in[7];
    const float* enc_ln_w   = (const float*)d_in[8];
    const float* enc_ln_b   = (const float*)d_in[9];
    const float* dec_attn_w = (const float*)d_in[10];
    const float* dec_attn_b = (const float*)d_in[11];
    const float* dec_w1     = (const float*)d_in[12];
    const float* dec_b1     = (const float*)d_in[13];
    const float* dec_w2     = (const float*)d_in[14];
    const float* dec_b2     = (const float*)d_in[15];
    const float* dec_ln_w   = (const float*)d_in[16];
    const float* dec_ln_b   = (const float*)d_in[17];
    const float* enc_norm_w = (const float*)d_in[18];
    const float* enc_norm_b = (const float*)d_in[19];
    const float* dec_norm_w = (const float*)d_in[20];
    const float* dec_norm_b = (const float*)d_in[21];
    const float* h2t_w      = (const float*)d_in[22];
    const float* h2t_b      = (const float*)d_in[23];
    const float* trans      = (const float*)d_in[24];
    (void)in_sizes; (void)n_in;

    float *x, *h, *mem, *y, *qkv, *t2, *tmp, *att, *ff, *feats;
    int* bptr;
    cudaGetSymbolAddress((void**)&x,     g_x);
    cudaGetSymbolAddress((void**)&h,     g_h);
    cudaGetSymbolAddress((void**)&mem,   g_mem);
    cudaGetSymbolAddress((void**)&y,     g_y);
    cudaGetSymbolAddress((void**)&qkv,   g_qkv);
    cudaGetSymbolAddress((void**)&t2,    g_t2);
    cudaGetSymbolAddress((void**)&tmp,   g_tmp);
    cudaGetSymbolAddress((void**)&att,   g_att);
    cudaGetSymbolAddress((void**)&ff,    g_ff);
    cudaGetSymbolAddress((void**)&feats, g_feats);
    cudaGetSymbolAddress((void**)&bptr,  g_bptr);

    float* q = qkv;
    float* k = qkv + (size_t)S_ * H_;
    float* v = qkv + (size_t)2 * S_ * H_;

    const float inv_sqrt_h = 0.044194173824159216f;  // 1/sqrt(512)

    const dim3 gQKV(H_ / 128, S_ / 128, 3);   // (4,16,3)
    const dim3 gSS(S_ / 128, S_ / 128);       // (16,16)
    const dim3 gSH64(H_ / 64, S_ / 128);      // (8,16)
    const dim3 gSF(F_ / 128, S_ / 128);       // (16,16)

    auto attn = [&](const float* qin, const float* kvin,
                    const float* W, const float* Bv, float* out) {
        gemm_qkv_kernel<<<gQKV, 256>>>(qin, kvin, W, Bv, qkv);
        gemm128_kernel<true, false><<<gSS, 256>>>(q, k, nullptr, att, S_, H_, inv_sqrt_h);
        softmax_kernel<<<S_, 256>>>(att);
        gemm12864_kernel<false><<<gSH64, 256>>>(att, v, nullptr, t2, H_, S_, 1.f);
        gemm12864_kernel<false><<<gSH64, 256>>>(t2, W + 3 * H_ * H_, Bv + 3 * H_, out, H_, H_, 1.f);
    };
    auto ln = [&](float* o, const float* a, const float* r,
                  const float* w, const float* b) {
        ln_kernel<<<S_ / 8, 256>>>(o, a, r, w, b);
    };

    // ---- embed ----
    embed_kernel<<<S_, 128>>>(x, sentence, embed);

    // ---- encoder ----
    const float* cur = x;
    for (int i = 0; i < L_; i++) {
        const float* W  = enc_attn_w + (size_t)i * 4 * H_ * H_;
        const float* Bv = enc_attn_b + (size_t)i * 4 * H_;
        attn(cur, cur, W, Bv, tmp);
        ln(h, tmp, cur, enc_ln_w + (size_t)i * 2 * H_, enc_ln_b + (size_t)i * 2 * H_);
        cur = h;
        gemm128_kernel<false, true><<<gSF, 256>>>(cur, enc_w1 + (size_t)i * H_ * F_,
                                                  enc_b1 + (size_t)i * F_, ff, F_, H_, 1.f);
        gemm12864_kernel<false><<<gSH64, 256>>>(ff, enc_w2 + (size_t)i * F_ * H_,
                                                enc_b2 + (size_t)i * H_, tmp, H_, F_, 1.f);
        ln(h, tmp, cur, enc_ln_w + (size_t)i * 2 * H_ + H_,
                        enc_ln_b + (size_t)i * 2 * H_ + H_);
    }
    ln(mem, h, nullptr, enc_norm_w, enc_norm_b);

    // ---- decoder ----
    cur = x;
    for (int i = 0; i < L_; i++) {
        const float* W  = dec_attn_w + (size_t)i * 8 * H_ * H_;
        const float* Bv = dec_attn_b + (size_t)i * 8 * H_;
        attn(cur, cur, W, Bv, tmp);                                    // self-attn
        ln(y, tmp, cur, dec_ln_w + (size_t)i * 3 * H_, dec_ln_b + (size_t)i * 3 * H_);
        attn(y, mem, W + 4 * H_ * H_, Bv + 4 * H_, tmp);               // cross-attn
        ln(y, tmp, y, dec_ln_w + (size_t)i * 3 * H_ + H_,
                      dec_ln_b + (size_t)i * 3 * H_ + H_);
        gemm128_kernel<false, true><<<gSF, 256>>>(y, dec_w1 + (size_t)i * H_ * F_,
                                                  dec_b1 + (size_t)i * F_, ff, F_, H_, 1.f);
        gemm12864_kernel<false><<<gSH64, 256>>>(ff, dec_w2 + (size_t)i * F_ * H_,
                                                dec_b2 + (size_t)i * H_, tmp, H_, F_, 1.f);
        ln(y, tmp, y, dec_ln_w + (size_t)i * 3 * H_ + 2 * H_,
                      dec_ln_b + (size_t)i * 3 * H_ + 2 * H_);
        cur = y;
    }
    ln(tmp, y, nullptr, dec_norm_w, dec_norm_b);

    // ---- feats + viterbi ----
    gemm64_kernel<false, false><<<dim3(1, S_ / 64), 256>>>(tmp, h2t_w, h2t_b, feats,
                                                           S_, T_, H_, 1.f);
    viterbi_kernel<<<1, 32>>>(feats, trans, bptr, (float*)d_out, out_size);
}

// round 5
// speedup vs baseline: 1.2073x; 1.2073x over previous
#include <cuda_runtime.h>
#include <math.h>
#include <stdint.h>

// Problem constants
#define S_ 2048
#define H_ 512
#define F_ 2048
#define T_ 32
#define L_ 6
#define START_TAG 30
#define STOP_TAG 31
#define NEG_ (-10000.0f)

// ---------------------------------------------------------------------------
// Static device scratch (no allocations allowed)
// ---------------------------------------------------------------------------
__device__ float g_x[S_ * H_];        // embeddings (kept for decoder input)
__device__ float g_h[S_ * H_];        // encoder stream
__device__ float g_mem[S_ * H_];      // encoder memory
__device__ float g_y[S_ * H_];        // decoder stream
__device__ float g_qkv[3 * S_ * H_];  // q,k,v packed
__device__ float g_t2[S_ * H_];       // att @ v
__device__ float g_tmp[S_ * H_];      // pre-LN sublayer output
__device__ float g_att[S_ * S_];      // attention scores (16 MB)
__device__ float g_ff[S_ * F_];       // FFN hidden (16 MB)
__device__ float g_feats[S_ * T_];
__device__ int   g_bptr[S_ * T_];

// ---------------------------------------------------------------------------
// tf32 helpers (3xTF32 split: v = hi + lo, both tf32-representable)
// ---------------------------------------------------------------------------
__device__ __forceinline__ void tf32_split(float v, unsigned& hi, unsigned& lo)
{
    asm("cvt.rna.tf32.f32 %0, %1;" : "=r"(hi) : "f"(v));
    float r = v - __uint_as_float(hi);
    asm("cvt.rna.tf32.f32 %0, %1;" : "=r"(lo) : "f"(r));
}

#define MMA_TF32(d, a, b)                                              \
    asm("mma.sync.aligned.m16n8k8.row.col.f32.tf32.tf32.f32 "          \
        "{%0,%1,%2,%3}, {%4,%5,%6,%7}, {%8,%9}, {%0,%1,%2,%3};"        \
        : "+f"((d)[0]), "+f"((d)[1]), "+f"((d)[2]), "+f"((d)[3])       \
        : "r"((a)[0]), "r"((a)[1]), "r"((a)[2]), "r"((a)[3]),          \
          "r"((b)[0]), "r"((b)[1]))

// ===========================================================================
// Tensor-core GEMM (3xTF32, fp32-accurate).
// C[M,N] = alpha * A[M,K] @ B (+ bias), optional ReLU.
// TRANSB=false: B is [K,N]. TRANSB=true: B is [N,K].
// CTA tile 128x64, 8 warps (warp grid 4m x 2n, warp tile 32x32), BK=16,
// double-buffered smem. Requires M%128==0, N%64==0, K%16==0.
// ===========================================================================
template <bool TRANSB, bool RELU>
__device__ __forceinline__ void mma_gemm_body(
    const float* __restrict__ A, const float* __restrict__ B,
    const float* __restrict__ bias, float* __restrict__ C,
    int N, int K, float alpha)
{
    __shared__ float As[2][128 * 20];                      // 128 rows x (16+4)
    __shared__ float Bs[2][TRANSB ? (64 * 20) : (16 * 68)];

    const int tid = threadIdx.x;
    const int m0 = blockIdx.y * 128;
    const int n0 = blockIdx.x * 64;

    // global->smem mappings
    const int arow = tid >> 2;          // 0..63 (and +64)
    const int acol = (tid & 3) * 4;     // 0,4,8,12
    const int bnr  = tid >> 4;          // 0..15   (B normal: [K,N] tile 16x64)
    const int bnc  = (tid & 15) * 4;    // 0..60
    const int btr  = tid >> 2;          // 0..63   (B trans: [N,K] tile 64x16)
    const int btc  = (tid & 3) * 4;

    // mma lane mapping
    const int lane = tid & 31;
    const int g  = lane >> 2;           // 0..7
    const int t4 = lane & 3;            // 0..3
    const int warpId = tid >> 5;
    const int wr = (warpId & 3) * 32;   // warp row offset in CTA tile
    const int wc = (warpId >> 2) * 32;  // warp col offset

    float4 ra0, ra1, rb0;

    // ---- prologue: load tile 0 ----
    ra0 = *(const float4*)(A + (size_t)(m0 + arow) * K + acol);
    ra1 = *(const float4*)(A + (size_t)(m0 + arow + 64) * K + acol);
    if (!TRANSB) rb0 = *(const float4*)(B + (size_t)bnr * N + n0 + bnc);
    else         rb0 = *(const float4*)(B + (size_t)(n0 + btr) * K + btc);

    *(float4*)&As[0][arow * 20 + acol]        = ra0;
    *(float4*)&As[0][(arow + 64) * 20 + acol] = ra1;
    if (!TRANSB) *(float4*)&Bs[0][bnr * 68 + bnc] = rb0;
    else         *(float4*)&Bs[0][btr * 20 + btc] = rb0;

    float acc[2][4][4];
#pragma unroll
    for (int i = 0; i < 2; i++)
#pragma unroll
        for (int j = 0; j < 4; j++)
#pragma unroll
            for (int r = 0; r < 4; r++) acc[i][j][r] = 0.f;

    const int nIter = K >> 4;
    for (int it = 0; it < nIter; it++) {
        const int cur = it & 1;
        __syncthreads();

        // prefetch next tile into registers
        if (it + 1 < nIter) {
            const int k0 = (it + 1) << 4;
            ra0 = *(const float4*)(A + (size_t)(m0 + arow) * K + k0 + acol);
            ra1 = *(const float4*)(A + (size_t)(m0 + arow + 64) * K + k0 + acol);
            if (!TRANSB) rb0 = *(const float4*)(B + (size_t)(k0 + bnr) * N + n0 + bnc);
            else         rb0 = *(const float4*)(B + (size_t)(n0 + btr) * K + k0 + btc);
        }

        // compute: 2 k-slices of 8
#pragma unroll
        for (int ks = 0; ks < 2; ks++) {
            const int k0 = ks * 8;

            unsigned ahi[2][4], alo[2][4];
#pragma unroll
            for (int mt = 0; mt < 2; mt++) {
                const int r0 = wr + mt * 16 + g;
                float a0 = As[cur][r0 * 20 + k0 + t4];
                float a1 = As[cur][(r0 + 8) * 20 + k0 + t4];
                float a2 = As[cur][r0 * 20 + k0 + t4 + 4];
                float a3 = As[cur][(r0 + 8) * 20 + k0 + t4 + 4];
                tf32_split(a0, ahi[mt][0], alo[mt][0]);
                tf32_split(a1, ahi[mt][1], alo[mt][1]);
                tf32_split(a2, ahi[mt][2], alo[mt][2]);
                tf32_split(a3, ahi[mt][3], alo[mt][3]);
            }

            unsigned bhi[4][2], blo[4][2];
#pragma unroll
            for (int nn = 0; nn < 4; nn++) {
                const int c = wc + nn * 8 + g;
                float b0, b1;
                if (!TRANSB) {
                    b0 = Bs[cur][(k0 + t4) * 68 + c];
                    b1 = Bs[cur][(k0 + t4 + 4) * 68 + c];
                } else {
                    b0 = Bs[cur][c * 20 + k0 + t4];
                    b1 = Bs[cur][c * 20 + k0 + t4 + 4];
                }
                tf32_split(b0, bhi[nn][0], blo[nn][0]);
                tf32_split(b1, bhi[nn][1], blo[nn][1]);
            }

#pragma unroll
            for (int mt = 0; mt < 2; mt++)
#pragma unroll
                for (int nn = 0; nn < 4; nn++) {
                    MMA_TF32(acc[mt][nn], alo[mt], bhi[nn]);
                    MMA_TF32(acc[mt][nn], ahi[mt], blo[nn]);
                    MMA_TF32(acc[mt][nn], ahi[mt], bhi[nn]);
                }
        }

        // stage next tile into other buffer
        if (it + 1 < nIter) {
            const int nb = cur ^ 1;
            *(float4*)&As[nb][arow * 20 + acol]        = ra0;
            *(float4*)&As[nb][(arow + 64) * 20 + acol] = ra1;
            if (!TRANSB) *(float4*)&Bs[nb][bnr * 68 + bnc] = rb0;
            else         *(float4*)&Bs[nb][btr * 20 + btc] = rb0;
        }
    }

    // ---- epilogue ----
#pragma unroll
    for (int mt = 0; mt < 2; mt++) {
        const int r0 = m0 + wr + mt * 16 + g;
#pragma unroll
        for (int nn = 0; nn < 4; nn++) {
            const int c = n0 + wc + nn * 8 + 2 * t4;
            float2 o0, o1;
            o0.x = acc[mt][nn][0] * alpha;
            o0.y = acc[mt][nn][1] * alpha;
            o1.x = acc[mt][nn][2] * alpha;
            o1.y = acc[mt][nn][3] * alpha;
            if (bias) {
                float bx = bias[c], by = bias[c + 1];
                o0.x += bx; o0.y += by;
                o1.x += bx; o1.y += by;
            }
            if (RELU) {
                o0.x = fmaxf(o0.x, 0.f); o0.y = fmaxf(o0.y, 0.f);
                o1.x = fmaxf(o1.x, 0.f); o1.y = fmaxf(o1.y, 0.f);
            }
            *(float2*)(C + (size_t)r0 * N + c)       = o0;
            *(float2*)(C + (size_t)(r0 + 8) * N + c) = o1;
        }
    }
}

template <bool TRANSB, bool RELU>
__global__ __launch_bounds__(256, 2) void mma_gemm_kernel(
    const float* __restrict__ A, const float* __restrict__ B,
    const float* __restrict__ bias, float* __restrict__ C,
    int N, int K, float alpha)
{
    mma_gemm_body<TRANSB, RELU>(A, B, bias, C, N, K, alpha);
}

// Batched QKV projection: blockIdx.z selects q (from qin) / k / v (from kvin).
__global__ __launch_bounds__(256, 2) void mma_qkv_kernel(
    const float* __restrict__ qin, const float* __restrict__ kvin,
    const float* __restrict__ W, const float* __restrict__ Bv,
    float* __restrict__ qkv)
{
    const int z = blockIdx.z;
    const float* A = (z == 0) ? qin : kvin;
    mma_gemm_body<false, false>(A, W + (size_t)z * H_ * H_, Bv + (size_t)z * H_,
                                qkv + (size_t)z * S_ * H_, H_, H_, 1.f);
}

// ---- 64x64x16 bounds-checked scalar fallback (used for h2t, N=32) ----
#define BM 64
#define BN 64
#define BK 16

template <bool TRANSB, bool RELU>
__global__ __launch_bounds__(256) void gemm64_kernel(
    const float* __restrict__ A, const float* __restrict__ B,
    const float* __restrict__ bias, float* __restrict__ C,
    int M, int N, int K, float alpha)
{
    __shared__ float As[BK][BM];
    __shared__ float Bs[BK][BN + 4];

    const int tid = threadIdx.x;
    const int m0 = blockIdx.y * BM;
    const int n0 = blockIdx.x * BN;
    const int tx = tid & 15;
    const int ty = tid >> 4;

    float acc[4][4];
#pragma unroll
    for (int i = 0; i < 4; i++)
#pragma unroll
        for (int j = 0; j < 4; j++) acc[i][j] = 0.f;

    for (int k0 = 0; k0 < K; k0 += BK) {
        {
            const int row = tid >> 2;
            const int col = (tid & 3) * 4;
            float4 av = make_float4(0.f, 0.f, 0.f, 0.f);
            if (m0 + row < M)
                av = *(const float4*)(A + (size_t)(m0 + row) * K + k0 + col);
            As[col + 0][row] = av.x;
            As[col + 1][row] = av.y;
            As[col + 2][row] = av.z;
            As[col + 3][row] = av.w;
        }
        if (!TRANSB) {
            const int row = tid >> 4;
            const int col = (tid & 15) * 4;
            float4 bv;
            if (n0 + col + 3 < N) {
                bv = *(const float4*)(B + (size_t)(k0 + row) * N + n0 + col);
            } else {
                float t0 = (n0 + col + 0 < N) ? B[(size_t)(k0 + row) * N + n0 + col + 0] : 0.f;
                float t1 = (n0 + col + 1 < N) ? B[(size_t)(k0 + row) * N + n0 + col + 1] : 0.f;
                float t2 = (n0 + col + 2 < N) ? B[(size_t)(k0 + row) * N + n0 + col + 2] : 0.f;
                float t3 = (n0 + col + 3 < N) ? B[(size_t)(k0 + row) * N + n0 + col + 3] : 0.f;
                bv = make_float4(t0, t1, t2, t3);
            }
            *(float4*)&Bs[row][col] = bv;
        } else {
            const int row = tid >> 2;
            const int col = (tid & 3) * 4;
            float4 bv = make_float4(0.f, 0.f, 0.f, 0.f);
            if (n0 + row < N)
                bv = *(const float4*)(B + (size_t)(n0 + row) * K + k0 + col);
            Bs[col + 0][row] = bv.x;
            Bs[col + 1][row] = bv.y;
            Bs[col + 2][row] = bv.z;
            Bs[col + 3][row] = bv.w;
        }
        __syncthreads();

#pragma unroll
        for (int kk = 0; kk < BK; kk++) {
            float4 a0 = *(const float4*)&As[kk][ty * 4];
            float4 b0 = *(const float4*)&Bs[kk][tx * 4];
            acc[0][0] += a0.x * b0.x; acc[0][1] += a0.x * b0.y; acc[0][2] += a0.x * b0.z; acc[0][3] += a0.x * b0.w;
            acc[1][0] += a0.y * b0.x; acc[1][1] += a0.y * b0.y; acc[1][2] += a0.y * b0.z; acc[1][3] += a0.y * b0.w;
            acc[2][0] += a0.z * b0.x; acc[2][1] += a0.z * b0.y; acc[2][2] += a0.z * b0.z; acc[2][3] += a0.z * b0.w;
            acc[3][0] += a0.w * b0.x; acc[3][1] += a0.w * b0.y; acc[3][2] += a0.w * b0.z; acc[3][3] += a0.w * b0.w;
        }
        __syncthreads();
    }

#pragma unroll
    for (int i = 0; i < 4; i++) {
        const int row = m0 + ty * 4 + i;
        if (row >= M) continue;
        const int col = n0 + tx * 4;
#pragma unroll
        for (int j = 0; j < 4; j++) {
            if (col + j < N) {
                float o = acc[i][j] * alpha;
                if (bias) o += bias[col + j];
                if (RELU) o = fmaxf(o, 0.f);
                C[(size_t)row * N + col + j] = o;
            }
        }
    }
}

// ---------------------------------------------------------------------------
// Row softmax over N = S_ columns. One block (256 thr) per row, in place.
// ---------------------------------------------------------------------------
__global__ __launch_bounds__(256) void softmax_kernel(float* __restrict__ x)
{
    const int N = S_;
    float* p = x + (size_t)blockIdx.x * N;
    const int tid = threadIdx.x;
    __shared__ float r1[8];
    __shared__ float r2[8];

    float mx = -3.4e38f;
    for (int c = tid; c < N; c += 256) mx = fmaxf(mx, p[c]);
#pragma unroll
    for (int o = 16; o; o >>= 1) mx = fmaxf(mx, __shfl_xor_sync(0xffffffffu, mx, o));
    if ((tid & 31) == 0) r1[tid >> 5] = mx;
    __syncthreads();
    mx = r1[0];
#pragma unroll
    for (int i = 1; i < 8; i++) mx = fmaxf(mx, r1[i]);

    float sum = 0.f;
    for (int c = tid; c < N; c += 256) {
        float e = expf(p[c] - mx);
        p[c] = e;
        sum += e;
    }
#pragma unroll
    for (int o = 16; o; o >>= 1) sum += __shfl_xor_sync(0xffffffffu, sum, o);
    if ((tid & 31) == 0) r2[tid >> 5] = sum;
    __syncthreads();
    sum = 0.f;
#pragma unroll
    for (int i = 0; i < 8; i++) sum += r2[i];
    const float inv = 1.f / sum;
    for (int c = tid; c < N; c += 256) p[c] *= inv;
}

// ---------------------------------------------------------------------------
// LayerNorm over H_=512: out = LN(a (+ res)) * w + b. One warp per row.
// ---------------------------------------------------------------------------
__global__ __launch_bounds__(256) void ln_kernel(
    float* __restrict__ out, const float* __restrict__ a,
    const float* __restrict__ res,
    const float* __restrict__ w, const float* __restrict__ b)
{
    const int gw = (blockIdx.x * blockDim.x + threadIdx.x) >> 5;
    const int lane = threadIdx.x & 31;
    if (gw >= S_) return;

    const float4* ap = (const float4*)(a + (size_t)gw * H_);
    const float4* rp = res ? (const float4*)(res + (size_t)gw * H_) : nullptr;

    float4 xv[4];
    float sum = 0.f;
#pragma unroll
    for (int i = 0; i < 4; i++) {
        float4 vv = ap[i * 32 + lane];
        if (rp) {
            float4 r = rp[i * 32 + lane];
            vv.x += r.x; vv.y += r.y; vv.z += r.z; vv.w += r.w;
        }
        xv[i] = vv;
        sum += vv.x + vv.y + vv.z + vv.w;
    }
#pragma unroll
    for (int o = 16; o; o >>= 1) sum += __shfl_xor_sync(0xffffffffu, sum, o);
    const float mean = sum * (1.f / H_);

    float var = 0.f;
#pragma unroll
    for (int i = 0; i < 4; i++) {
        float dx = xv[i].x - mean; var += dx * dx;
        dx = xv[i].y - mean; var += dx * dx;
        dx = xv[i].z - mean; var += dx * dx;
        dx = xv[i].w - mean; var += dx * dx;
    }
#pragma unroll
    for (int o = 16; o; o >>= 1) var += __shfl_xor_sync(0xffffffffu, var, o);
    const float rs = rsqrtf(var * (1.f / H_) + 1e-5f);

    float4* op = (float4*)(out + (size_t)gw * H_);
    const float4* wp = (const float4*)w;
    const float4* bp = (const float4*)b;
#pragma unroll
    for (int i = 0; i < 4; i++) {
        const int idx = i * 32 + lane;
        float4 wv = wp[idx];
        float4 bv = bp[idx];
        float4 o;
        o.x = (xv[i].x - mean) * rs * wv.x + bv.x;
        o.y = (xv[i].y - mean) * rs * wv.y + bv.y;
        o.z = (xv[i].z - mean) * rs * wv.z + bv.z;
        o.w = (xv[i].w - mean) * rs * wv.w + bv.w;
        op[idx] = o;
    }
}

// ---------------------------------------------------------------------------
// Embedding gather
// ---------------------------------------------------------------------------
__global__ __launch_bounds__(128) void embed_kernel(
    float* __restrict__ x, const int* __restrict__ sent,
    const float* __restrict__ embed)
{
    const int s = blockIdx.x;
    const int t = threadIdx.x;
    const float4* src = (const float4*)(embed + (size_t)sent[s] * H_);
    ((float4*)(x + (size_t)s * H_))[t] = src[t];
}

// ---------------------------------------------------------------------------
// Viterbi: single warp. Matches jnp.argmax first-max semantics via strict >.
// ---------------------------------------------------------------------------
__global__ void viterbi_kernel(const float* __restrict__ feats,
                               const float* __restrict__ trans,
                               int* __restrict__ bptr,
                               float* __restrict__ out, int out_size)
{
    const int j = threadIdx.x;
    __shared__ float fv[T_];
    __shared__ float terms[T_];

    float tr[T_];
#pragma unroll
    for (int i = 0; i < T_; i++) tr[i] = trans[j * T_ + i];

    fv[j] = (j == START_TAG) ? 0.f : NEG_;
    __syncwarp();

    for (int t = 0; t < S_; t++) {
        float best = -3.4e38f;
        int bi = 0;
#pragma unroll
        for (int i = 0; i < T_; i++) {
            float sc = fv[i] + tr[i];
            if (sc > best) { best = sc; bi = i; }
        }
        float nf = best + feats[t * T_ + j];
        bptr[t * T_ + j] = bi;
        __syncwarp();
        fv[j] = nf;
        __syncwarp();
    }

    terms[j] = fv[j] + trans[STOP_TAG * T_ + j];
    __syncwarp();

    if (j == 0) {
        float best = terms[0];
        int bi = 0;
#pragma unroll
        for (int i = 1; i < T_; i++)
            if (terms[i] > best) { best = terms[i]; bi = i; }

        int tag = bi;
        if (out_size >= S_ + 1) {
            out[0] = best;
            for (int t = S_ - 1; t >= 0; t--) {
                out[1 + t] = (float)tag;
                tag = bptr[t * T_ + tag];
            }
        } else if (out_size == S_) {
            for (int t = S_ - 1; t >= 0; t--) {
                out[t] = (float)tag;
                tag = bptr[t * T_ + tag];
            }
        } else {
            out[0] = best;
        }
    }
}

// ---------------------------------------------------------------------------
// Host orchestration
// ---------------------------------------------------------------------------
extern "C" void kernel_launch(void* const* d_in, const int* in_sizes, int n_in,
                              void* d_out, int out_size)
{
    const int*   sentence   = (const int*)  d_in[0];
    const float* embed      = (const float*)d_in[1];
    const float* enc_attn_w = (const float*)d_in[2];
    const float* enc_attn_b = (const float*)d_in[3];
    const float* enc_w1     = (const float*)d_in[4];
    const float* enc_b1     = (const float*)d_in[5];
    const float* enc_w2     = (const float*)d_in[6];
    const float* enc_b2     = (const float*)d_in[7];
    const float* enc_ln_w   = (const float*)d_in[8];
    const float* enc_ln_b   = (const float*)d_in[9];
    const float* dec_attn_w = (const float*)d_in[10];
    const float* dec_attn_b = (const float*)d_in[11];
    const float* dec_w1     = (const float*)d_in[12];
    const float* dec_b1     = (const float*)d_in[13];
    const float* dec_w2     = (const float*)d_in[14];
    const float* dec_b2     = (const float*)d_in[15];
    const float* dec_ln_w   = (const float*)d_in[16];
    const float* dec_ln_b   = (const float*)d_in[17];
    const float* enc_norm_w = (const float*)d_in[18];
    const float* enc_norm_b = (const float*)d_in[19];
    const float* dec_norm_w = (const float*)d_in[20];
    const float* dec_norm_b = (const float*)d_in[21];
    const float* h2t_w      = (const float*)d_in[22];
    const float* h2t_b      = (const float*)d_in[23];
    const float* trans      = (const float*)d_in[24];
    (void)in_sizes; (void)n_in;

    float *x, *h, *mem, *y, *qkv, *t2, *tmp, *att, *ff, *feats;
    int* bptr;
    cudaGetSymbolAddress((void**)&x,     g_x);
    cudaGetSymbolAddress((void**)&h,     g_h);
    cudaGetSymbolAddress((void**)&mem,   g_mem);
    cudaGetSymbolAddress((void**)&y,     g_y);
    cudaGetSymbolAddress((void**)&qkv,   g_qkv);
    cudaGetSymbolAddress((void**)&t2,    g_t2);
    cudaGetSymbolAddress((void**)&tmp,   g_tmp);
    cudaGetSymbolAddress((void**)&att,   g_att);
    cudaGetSymbolAddress((void**)&ff,    g_ff);
    cudaGetSymbolAddress((void**)&feats, g_feats);
    cudaGetSymbolAddress((void**)&bptr,  g_bptr);

    float* q = qkv;
    float* k = qkv + (size_t)S_ * H_;
    float* v = qkv + (size_t)2 * S_ * H_;

    const float inv_sqrt_h = 0.044194173824159216f;  // 1/sqrt(512)

    const dim3 gQKV(H_ / 64, S_ / 128, 3);    // (8,16,3)
    const dim3 gSS(S_ / 64, S_ / 128);        // (32,16)
    const dim3 gSH(H_ / 64, S_ / 128);        // (8,16)
    const dim3 gSF(F_ / 64, S_ / 128);        // (32,16)

    auto attn = [&](const float* qin, const float* kvin,
                    const float* W, const float* Bv, float* out) {
        mma_qkv_kernel<<<gQKV, 256>>>(qin, kvin, W, Bv, qkv);
        mma_gemm_kernel<true, false><<<gSS, 256>>>(q, k, nullptr, att, S_, H_, inv_sqrt_h);
        softmax_kernel<<<S_, 256>>>(att);
        mma_gemm_kernel<false, false><<<gSH, 256>>>(att, v, nullptr, t2, H_, S_, 1.f);
        mma_gemm_kernel<false, false><<<gSH, 256>>>(t2, W + 3 * H_ * H_, Bv + 3 * H_,
                                                    out, H_, H_, 1.f);
    };
    auto ln = [&](float* o, const float* a, const float* r,
                  const float* w, const float* b) {
        ln_kernel<<<S_ / 8, 256>>>(o, a, r, w, b);
    };

    // ---- embed ----
    embed_kernel<<<S_, 128>>>(x, sentence, embed);

    // ---- encoder ----
    const float* cur = x;
    for (int i = 0; i < L_; i++) {
        const float* W  = enc_attn_w + (size_t)i * 4 * H_ * H_;
        const float* Bv = enc_attn_b + (size_t)i * 4 * H_;
        attn(cur, cur, W, Bv, tmp);
        ln(h, tmp, cur, enc_ln_w + (size_t)i * 2 * H_, enc_ln_b + (size_t)i * 2 * H_);
        cur = h;
        mma_gemm_kernel<false, true><<<gSF, 256>>>(cur, enc_w1 + (size_t)i * H_ * F_,
                                                   enc_b1 + (size_t)i * F_, ff, F_, H_, 1.f);
        mma_gemm_kernel<false, false><<<gSH, 256>>>(ff, enc_w2 + (size_t)i * F_ * H_,
                                                    enc_b2 + (size_t)i * H_, tmp, H_, F_, 1.f);
        ln(h, tmp, cur, enc_ln_w + (size_t)i * 2 * H_ + H_,
                        enc_ln_b + (size_t)i * 2 * H_ + H_);
    }
    ln(mem, h, nullptr, enc_norm_w, enc_norm_b);

    // ---- decoder ----
    cur = x;
    for (int i = 0; i < L_; i++) {
        const float* W  = dec_attn_w + (size_t)i * 8 * H_ * H_;
        const float* Bv = dec_attn_b + (size_t)i * 8 * H_;
        attn(cur, cur, W, Bv, tmp);                                    // self-attn
        ln(y, tmp, cur, dec_ln_w + (size_t)i * 3 * H_, dec_ln_b + (size_t)i * 3 * H_);
        attn(y, mem, W + 4 * H_ * H_, Bv + 4 * H_, tmp);               // cross-attn
        ln(y, tmp, y, dec_ln_w + (size_t)i * 3 * H_ + H_,
                      dec_ln_b + (size_t)i * 3 * H_ + H_);
        mma_gemm_kernel<false, true><<<gSF, 256>>>(y, dec_w1 + (size_t)i * H_ * F_,
                                                   dec_b1 + (size_t)i * F_, ff, F_, H_, 1.f);
        mma_gemm_kernel<false, false><<<gSH, 256>>>(ff, dec_w2 + (size_t)i * F_ * H_,
                                                    dec_b2 + (size_t)i * H_, tmp, H_, F_, 1.f);
        ln(y, tmp, y, dec_ln_w + (size_t)i * 3 * H_ + 2 * H_,
                      dec_ln_b + (size_t)i * 3 * H_ + 2 * H_);
        cur = y;
    }
    ln(tmp, y, nullptr, dec_norm_w, dec_norm_b);

    // ---- feats + viterbi ----
    gemm64_kernel<false, false><<<dim3(1, S_ / 64), 256>>>(tmp, h2t_w, h2t_b, feats,
                                                           S_, T_, H_, 1.f);
    viterbi_kernel<<<1, 32>>>(feats, trans, bptr, (float*)d_out, out_size);
}